// round 14
// baseline (speedup 1.0000x reference)
#include <cuda_runtime.h>
#include <math.h>

#define T 64
#define THREADS 256
#define PITCH 65   // +1 float pad; mirror-phase LDS is 2-way conflicted (measured-OK)

// Uncompress packed strict-upper-triangle vector (row-major, j>i) into a full
// symmetric n x n matrix with unit diagonal.
//   idx(i,j) = i*(n-1) - i*(i-1)/2 + (j - i - 1)
//
// FINAL KERNEL — R5 configuration, converged optimum of a 10-round sweep
// (69.1/69.5/69.3us across three reproduction runs; 96.3us baseline):
//   - triangular grid: one block per upper-triangle 64x64 tile (bj >= bi),
//     zero dead blocks
//   - phase 1: coalesced plain LDG from comp -> forward to STG.32 upper tile
//     from registers + smem stash (ptxas front-batches ~16 LDGs)
//   - phase 2: float4 column-gather from smem -> STG.128 mirror tile
//   - __launch_bounds__(256, 6): regs-40 / occ-70%, the measured peak of
//     (per-thread LDG batch depth x resident warps): 64r/47%->72.2,
//     40r/70%->69.1, 32r/92%->71.3
// Measured and REJECTED: cp.async loads (74.2), 128x128 tiles (89.8),
// __stcs stores (69.7), column-split pipeline (73.7), __ldcs loads (110.4 —
// misaligned packed reads share cache lines across warps/tiles; default
// caching earns those hits, evict-first destroys them).
__global__ void __launch_bounds__(THREADS, 6)
uncompress_sym_kernel(const float* __restrict__ comp,
                      float* __restrict__ out,
                      int n, int nb) {
    __shared__ float s[T * PITCH];

    // Linear block id -> (bi, bj) in the upper triangle (row-major, incl diag).
    // start(bi) = bi*(2*nb - bi + 1)/2
    const int t = blockIdx.x;
    const float ff = (float)nb + 0.5f;
    int bi = (int)(ff - sqrtf(fmaxf(ff * ff - 2.0f * (float)t, 0.0f)));
    if (bi > nb - 1) bi = nb - 1;
    if (bi < 0) bi = 0;
    while (bi + 1 <= nb - 1 && ((bi + 1) * (2 * nb - bi)) / 2 <= t) bi++;
    while (bi > 0 && (bi * (2 * nb - bi + 1)) / 2 > t) bi--;
    const int bj = bi + (t - (bi * (2 * nb - bi + 1)) / 2);

    const int i0 = bi * T;
    const int j0 = bj * T;
    const int tid = threadIdx.x;

    if (bi != bj) {
        // Phase 1: coalesced load from comp, direct upper-tile store, smem stash.
        #pragma unroll
        for (int it = 0; it < (T * T) / THREADS; it++) {
            const int idx = it * THREADS + tid;
            const int r = idx >> 6;       // row within tile
            const int c = idx & 63;       // col within tile
            const int i = i0 + r;
            const int j = j0 + c;
            const int ci = i * (n - 1) - ((i * (i - 1)) >> 1) + (j - i - 1);
            const float v = comp[ci];                 // coalesced (contig in j)
            s[r * PITCH + c] = v;
            out[(size_t)i * n + j] = v;               // coalesced 128B/warp
        }
        __syncthreads();
        // Phase 2: mirror tile out[j][i] = tile^T, float4 column gather
        // (2-way LDS conflict with PITCH=65), STG.128 (i0 + c4 mult of 4).
        #pragma unroll
        for (int it = 0; it < (T * T) / (THREADS * 4); it++) {
            const int idx = it * THREADS + tid;
            const int r  = idx >> 4;            // row within mirror tile (0..63)
            const int c4 = (idx & 15) << 2;     // starting col (multiple of 4)
            float4 v;
            v.x = s[(c4 + 0) * PITCH + r];
            v.y = s[(c4 + 1) * PITCH + r];
            v.z = s[(c4 + 2) * PITCH + r];
            v.w = s[(c4 + 3) * PITCH + r];
            *(float4*)&out[(size_t)(j0 + r) * n + (i0 + c4)] = v;
        }
    } else {
        // Diagonal tile (128 of 8256 blocks): load strict upper, mirror in smem.
        #pragma unroll
        for (int it = 0; it < (T * T) / THREADS; it++) {
            const int idx = it * THREADS + tid;
            const int r = idx >> 6;
            const int c = idx & 63;
            const int i = i0 + r;
            const int j = j0 + c;
            float v = 0.0f;
            if (j > i) {
                const int ci = i * (n - 1) - ((i * (i - 1)) >> 1) + (j - i - 1);
                v = comp[ci];
            }
            s[r * PITCH + c] = v;
        }
        __syncthreads();
        #pragma unroll
        for (int it = 0; it < (T * T) / THREADS; it++) {
            const int idx = it * THREADS + tid;
            const int r = idx >> 6;
            const int c = idx & 63;
            float v;
            if (c > r)       v = s[r * PITCH + c];
            else if (c == r) v = 1.0f;
            else             v = s[c * PITCH + r];
            out[(size_t)(i0 + r) * n + (j0 + c)] = v;
        }
    }
}

extern "C" void kernel_launch(void* const* d_in, const int* in_sizes, int n_in,
                              void* d_out, int out_size) {
    const float* comp = (const float*)d_in[0];
    float* out = (float*)d_out;

    // n = round(sqrt(2m)) + 1 — MUST be double: sqrt(2*33550336) = 8191.49998,
    // which rounds to exactly 8191.5 in fp32 and would give n=8193 (OOB).
    const long long m = (long long)in_sizes[0];
    const int n = (int)llround(sqrt(2.0 * (double)m)) + 1;  // 8192
    const int nb = n / T;                                   // 128

    const int nblocks = nb * (nb + 1) / 2;                  // 8256
    uncompress_sym_kernel<<<nblocks, THREADS>>>(comp, out, n, nb);
}

// round 15
// speedup vs baseline: 1.1003x; 1.1003x over previous
#include <cuda_runtime.h>
#include <math.h>

#define T 64
#define THREADS 256
#define PITCH 65   // +1 float pad; mirror-phase LDS is 2-way conflicted (measured-OK)

// Uncompress packed strict-upper-triangle vector (row-major, j>i) into a full
// symmetric n x n matrix with unit diagonal.
//   idx(i,j) = i*(n-1) - i*(i-1)/2 + (j - i - 1)
//
// FINAL KERNEL — R5 configuration, converged optimum of the session sweep.
// Timing distribution across 4 identical-source runs: 69.1/69.5/69.3/76.2us
// (the 76.2 outlier had identical regs/occ but inflated SM-domain ncu
// percentages -> DVFS clock-state variance, not a code effect).
//   - triangular grid: one block per upper-triangle 64x64 tile (bj >= bi)
//   - phase 1: coalesced plain LDG from comp -> forward to STG.32 upper tile
//     from registers + smem stash (ptxas front-batches ~16 LDGs)
//   - phase 2: float4 column-gather from smem -> STG.128 mirror tile
//   - __launch_bounds__(256, 6): regs-40 / occ-70%, measured peak of
//     (per-thread LDG batch depth x resident warps)
// Measured and REJECTED: cp.async loads (74.2), 128x128 tiles (89.8),
// __stcs stores (neutral), column-split pipeline (73.7), __ldcs loads
// (110.4 — misaligned packed reads share cache lines across warps/tiles;
// default caching earns those hits, evict-first destroys them).
__global__ void __launch_bounds__(THREADS, 6)
uncompress_sym_kernel(const float* __restrict__ comp,
                      float* __restrict__ out,
                      int n, int nb) {
    __shared__ float s[T * PITCH];

    // Linear block id -> (bi, bj) in the upper triangle (row-major, incl diag).
    // start(bi) = bi*(2*nb - bi + 1)/2
    const int t = blockIdx.x;
    const float ff = (float)nb + 0.5f;
    int bi = (int)(ff - sqrtf(fmaxf(ff * ff - 2.0f * (float)t, 0.0f)));
    if (bi > nb - 1) bi = nb - 1;
    if (bi < 0) bi = 0;
    while (bi + 1 <= nb - 1 && ((bi + 1) * (2 * nb - bi)) / 2 <= t) bi++;
    while (bi > 0 && (bi * (2 * nb - bi + 1)) / 2 > t) bi--;
    const int bj = bi + (t - (bi * (2 * nb - bi + 1)) / 2);

    const int i0 = bi * T;
    const int j0 = bj * T;
    const int tid = threadIdx.x;

    if (bi != bj) {
        // Phase 1: coalesced load from comp, direct upper-tile store, smem stash.
        #pragma unroll
        for (int it = 0; it < (T * T) / THREADS; it++) {
            const int idx = it * THREADS + tid;
            const int r = idx >> 6;       // row within tile
            const int c = idx & 63;       // col within tile
            const int i = i0 + r;
            const int j = j0 + c;
            const int ci = i * (n - 1) - ((i * (i - 1)) >> 1) + (j - i - 1);
            const float v = comp[ci];                 // coalesced (contig in j)
            s[r * PITCH + c] = v;
            out[(size_t)i * n + j] = v;               // coalesced 128B/warp
        }
        __syncthreads();
        // Phase 2: mirror tile out[j][i] = tile^T, float4 column gather
        // (2-way LDS conflict with PITCH=65), STG.128 (i0 + c4 mult of 4).
        #pragma unroll
        for (int it = 0; it < (T * T) / (THREADS * 4); it++) {
            const int idx = it * THREADS + tid;
            const int r  = idx >> 4;            // row within mirror tile (0..63)
            const int c4 = (idx & 15) << 2;     // starting col (multiple of 4)
            float4 v;
            v.x = s[(c4 + 0) * PITCH + r];
            v.y = s[(c4 + 1) * PITCH + r];
            v.z = s[(c4 + 2) * PITCH + r];
            v.w = s[(c4 + 3) * PITCH + r];
            *(float4*)&out[(size_t)(j0 + r) * n + (i0 + c4)] = v;
        }
    } else {
        // Diagonal tile (128 of 8256 blocks): load strict upper, mirror in smem.
        #pragma unroll
        for (int it = 0; it < (T * T) / THREADS; it++) {
            const int idx = it * THREADS + tid;
            const int r = idx >> 6;
            const int c = idx & 63;
            const int i = i0 + r;
            const int j = j0 + c;
            float v = 0.0f;
            if (j > i) {
                const int ci = i * (n - 1) - ((i * (i - 1)) >> 1) + (j - i - 1);
                v = comp[ci];
            }
            s[r * PITCH + c] = v;
        }
        __syncthreads();
        #pragma unroll
        for (int it = 0; it < (T * T) / THREADS; it++) {
            const int idx = it * THREADS + tid;
            const int r = idx >> 6;
            const int c = idx & 63;
            float v;
            if (c > r)       v = s[r * PITCH + c];
            else if (c == r) v = 1.0f;
            else             v = s[c * PITCH + r];
            out[(size_t)(i0 + r) * n + (j0 + c)] = v;
        }
    }
}

extern "C" void kernel_launch(void* const* d_in, const int* in_sizes, int n_in,
                              void* d_out, int out_size) {
    const float* comp = (const float*)d_in[0];
    float* out = (float*)d_out;

    // n = round(sqrt(2m)) + 1 — MUST be double: sqrt(2*33550336) = 8191.49998,
    // which rounds to exactly 8191.5 in fp32 and would give n=8193 (OOB).
    const long long m = (long long)in_sizes[0];
    const int n = (int)llround(sqrt(2.0 * (double)m)) + 1;  // 8192
    const int nb = n / T;                                   // 128

    const int nblocks = nb * (nb + 1) / 2;                  // 8256
    uncompress_sym_kernel<<<nblocks, THREADS>>>(comp, out, n, nb);
}

// round 16
// speedup vs baseline: 1.1116x; 1.0103x over previous
#include <cuda_runtime.h>
#include <math.h>

#define T 64
#define THREADS 256
#define PITCH 65   // +1 float pad; mirror-phase LDS is 2-way conflicted (measured-OK)

// Uncompress packed strict-upper-triangle vector (row-major, j>i) into a full
// symmetric n x n matrix with unit diagonal.
//   idx(i,j) = i*(n-1) - i*(i-1)/2 + (j - i - 1)
//
// FINAL KERNEL — converged optimum of the session sweep. Timing distribution
// across 5 identical-source runs: 69.1/69.5/69.3/76.2/69.2us (median 69.3;
// the 76.2 outlier was DVFS clock-state variance, confirmed by reversion).
//   - triangular grid: one block per upper-triangle 64x64 tile (bj >= bi),
//     zero dead blocks
//   - phase 1: coalesced plain LDG from comp -> forward to STG.32 upper tile
//     from registers + smem stash (ptxas front-batches ~16 LDGs)
//   - phase 2: float4 column-gather from smem -> STG.128 mirror tile
//   - __launch_bounds__(256, 6): regs-40 / occ-70%, measured peak of
//     (per-thread LDG batch depth x resident warps): 64r/47%->72.2,
//     40r/70%->69.1, 32r/92%->71.3
// Measured and REJECTED: cp.async loads (74.2), 128x128 tiles (89.8),
// __stcs stores (neutral), column-split pipeline (73.7), __ldcs loads
// (110.4 — misaligned packed reads share cache lines across warps/tiles;
// default caching earns those hits, evict-first destroys them).
__global__ void __launch_bounds__(THREADS, 6)
uncompress_sym_kernel(const float* __restrict__ comp,
                      float* __restrict__ out,
                      int n, int nb) {
    __shared__ float s[T * PITCH];

    // Linear block id -> (bi, bj) in the upper triangle (row-major, incl diag).
    // start(bi) = bi*(2*nb - bi + 1)/2
    const int t = blockIdx.x;
    const float ff = (float)nb + 0.5f;
    int bi = (int)(ff - sqrtf(fmaxf(ff * ff - 2.0f * (float)t, 0.0f)));
    if (bi > nb - 1) bi = nb - 1;
    if (bi < 0) bi = 0;
    while (bi + 1 <= nb - 1 && ((bi + 1) * (2 * nb - bi)) / 2 <= t) bi++;
    while (bi > 0 && (bi * (2 * nb - bi + 1)) / 2 > t) bi--;
    const int bj = bi + (t - (bi * (2 * nb - bi + 1)) / 2);

    const int i0 = bi * T;
    const int j0 = bj * T;
    const int tid = threadIdx.x;

    if (bi != bj) {
        // Phase 1: coalesced load from comp, direct upper-tile store, smem stash.
        #pragma unroll
        for (int it = 0; it < (T * T) / THREADS; it++) {
            const int idx = it * THREADS + tid;
            const int r = idx >> 6;       // row within tile
            const int c = idx & 63;       // col within tile
            const int i = i0 + r;
            const int j = j0 + c;
            const int ci = i * (n - 1) - ((i * (i - 1)) >> 1) + (j - i - 1);
            const float v = comp[ci];                 // coalesced (contig in j)
            s[r * PITCH + c] = v;
            out[(size_t)i * n + j] = v;               // coalesced 128B/warp
        }
        __syncthreads();
        // Phase 2: mirror tile out[j][i] = tile^T, float4 column gather
        // (2-way LDS conflict with PITCH=65), STG.128 (i0 + c4 mult of 4).
        #pragma unroll
        for (int it = 0; it < (T * T) / (THREADS * 4); it++) {
            const int idx = it * THREADS + tid;
            const int r  = idx >> 4;            // row within mirror tile (0..63)
            const int c4 = (idx & 15) << 2;     // starting col (multiple of 4)
            float4 v;
            v.x = s[(c4 + 0) * PITCH + r];
            v.y = s[(c4 + 1) * PITCH + r];
            v.z = s[(c4 + 2) * PITCH + r];
            v.w = s[(c4 + 3) * PITCH + r];
            *(float4*)&out[(size_t)(j0 + r) * n + (i0 + c4)] = v;
        }
    } else {
        // Diagonal tile (128 of 8256 blocks): load strict upper, mirror in smem.
        #pragma unroll
        for (int it = 0; it < (T * T) / THREADS; it++) {
            const int idx = it * THREADS + tid;
            const int r = idx >> 6;
            const int c = idx & 63;
            const int i = i0 + r;
            const int j = j0 + c;
            float v = 0.0f;
            if (j > i) {
                const int ci = i * (n - 1) - ((i * (i - 1)) >> 1) + (j - i - 1);
                v = comp[ci];
            }
            s[r * PITCH + c] = v;
        }
        __syncthreads();
        #pragma unroll
        for (int it = 0; it < (T * T) / THREADS; it++) {
            const int idx = it * THREADS + tid;
            const int r = idx >> 6;
            const int c = idx & 63;
            float v;
            if (c > r)       v = s[r * PITCH + c];
            else if (c == r) v = 1.0f;
            else             v = s[c * PITCH + r];
            out[(size_t)(i0 + r) * n + (j0 + c)] = v;
        }
    }
}

extern "C" void kernel_launch(void* const* d_in, const int* in_sizes, int n_in,
                              void* d_out, int out_size) {
    const float* comp = (const float*)d_in[0];
    float* out = (float*)d_out;

    // n = round(sqrt(2m)) + 1 — MUST be double: sqrt(2*33550336) = 8191.49998,
    // which rounds to exactly 8191.5 in fp32 and would give n=8193 (OOB).
    const long long m = (long long)in_sizes[0];
    const int n = (int)llround(sqrt(2.0 * (double)m)) + 1;  // 8192
    const int nb = n / T;                                   // 128

    const int nblocks = nb * (nb + 1) / 2;                  // 8256
    uncompress_sym_kernel<<<nblocks, THREADS>>>(comp, out, n, nb);
}

// round 17
// speedup vs baseline: 1.1211x; 1.0085x over previous
#include <cuda_runtime.h>
#include <math.h>

#define T 64
#define THREADS 256
#define PITCH 65   // +1 float pad; mirror-phase LDS is 2-way conflicted (measured-OK)

// Uncompress packed strict-upper-triangle vector (row-major, j>i) into a full
// symmetric n x n matrix with unit diagonal.
//   idx(i,j) = i*(n-1) - i*(i-1)/2 + (j - i - 1)
//
// R17 = converged R5 config with ONE remaining micro-lever: phase-1 upper-tile
// stores vectorized to STG.128 (was 16x STG.32/thread; now 4x STG.128/thread,
// each thread owns a 16B row chunk: 4 scalar LDG -> pack float4 -> 1 store).
// comp loads stay scalar (packed-triangle offsets are not 16B-aligned).
// Everything proven is preserved: triangular grid, plain LDG (cache-default),
// smem stash + float4 transpose, __launch_bounds__(256, 6) / regs-40 / occ-70%.
// Prior rejections: cp.async (74.2), T=128 (89.8), __stcs (neutral),
// column-split pipeline (73.7), __ldcs (110.4).
__global__ void __launch_bounds__(THREADS, 6)
uncompress_sym_kernel(const float* __restrict__ comp,
                      float* __restrict__ out,
                      int n, int nb) {
    __shared__ float s[T * PITCH];

    // Linear block id -> (bi, bj) in the upper triangle (row-major, incl diag).
    // start(bi) = bi*(2*nb - bi + 1)/2
    const int t = blockIdx.x;
    const float ff = (float)nb + 0.5f;
    int bi = (int)(ff - sqrtf(fmaxf(ff * ff - 2.0f * (float)t, 0.0f)));
    if (bi > nb - 1) bi = nb - 1;
    if (bi < 0) bi = 0;
    while (bi + 1 <= nb - 1 && ((bi + 1) * (2 * nb - bi)) / 2 <= t) bi++;
    while (bi > 0 && (bi * (2 * nb - bi + 1)) / 2 > t) bi--;
    const int bj = bi + (t - (bi * (2 * nb - bi + 1)) / 2);

    const int i0 = bi * T;
    const int j0 = bj * T;
    const int tid = threadIdx.x;

    if (bi != bj) {
        // Phase 1: each thread covers a 16B chunk of one tile row.
        // 4 scalar LDG (unaligned packed source) -> smem stash -> 1 STG.128.
        #pragma unroll
        for (int it = 0; it < (T * T) / (THREADS * 4); it++) {   // 4 iters
            const int idx = it * THREADS + tid;
            const int r  = idx >> 4;            // row within tile (16 rows/iter)
            const int c4 = (idx & 15) << 2;     // starting col: 0,4,...,60
            const int i = i0 + r;
            const int j = j0 + c4;
            const int ci = i * (n - 1) - ((i * (i - 1)) >> 1) + (j - i - 1);
            float4 v;
            v.x = comp[ci + 0];
            v.y = comp[ci + 1];
            v.z = comp[ci + 2];
            v.w = comp[ci + 3];
            s[r * PITCH + c4 + 0] = v.x;
            s[r * PITCH + c4 + 1] = v.y;
            s[r * PITCH + c4 + 2] = v.z;
            s[r * PITCH + c4 + 3] = v.w;
            *(float4*)&out[(size_t)i * n + j] = v;     // STG.128, coalesced
        }
        __syncthreads();
        // Phase 2: mirror tile out[j][i] = tile^T, float4 column gather
        // (2-way LDS conflict with PITCH=65), STG.128 (i0 + c4 mult of 4).
        #pragma unroll
        for (int it = 0; it < (T * T) / (THREADS * 4); it++) {
            const int idx = it * THREADS + tid;
            const int r  = idx >> 4;            // row within mirror tile (0..63)
            const int c4 = (idx & 15) << 2;     // starting col (multiple of 4)
            float4 v;
            v.x = s[(c4 + 0) * PITCH + r];
            v.y = s[(c4 + 1) * PITCH + r];
            v.z = s[(c4 + 2) * PITCH + r];
            v.w = s[(c4 + 3) * PITCH + r];
            *(float4*)&out[(size_t)(j0 + r) * n + (i0 + c4)] = v;
        }
    } else {
        // Diagonal tile (128 of 8256 blocks): load strict upper, mirror in smem.
        #pragma unroll
        for (int it = 0; it < (T * T) / THREADS; it++) {
            const int idx = it * THREADS + tid;
            const int r = idx >> 6;
            const int c = idx & 63;
            const int i = i0 + r;
            const int j = j0 + c;
            float v = 0.0f;
            if (j > i) {
                const int ci = i * (n - 1) - ((i * (i - 1)) >> 1) + (j - i - 1);
                v = comp[ci];
            }
            s[r * PITCH + c] = v;
        }
        __syncthreads();
        #pragma unroll
        for (int it = 0; it < (T * T) / THREADS; it++) {
            const int idx = it * THREADS + tid;
            const int r = idx >> 6;
            const int c = idx & 63;
            float v;
            if (c > r)       v = s[r * PITCH + c];
            else if (c == r) v = 1.0f;
            else             v = s[c * PITCH + r];
            out[(size_t)(i0 + r) * n + (j0 + c)] = v;
        }
    }
}

extern "C" void kernel_launch(void* const* d_in, const int* in_sizes, int n_in,
                              void* d_out, int out_size) {
    const float* comp = (const float*)d_in[0];
    float* out = (float*)d_out;

    // n = round(sqrt(2m)) + 1 — MUST be double: sqrt(2*33550336) = 8191.49998,
    // which rounds to exactly 8191.5 in fp32 and would give n=8193 (OOB).
    const long long m = (long long)in_sizes[0];
    const int n = (int)llround(sqrt(2.0 * (double)m)) + 1;  // 8192
    const int nb = n / T;                                   // 128

    const int nblocks = nb * (nb + 1) / 2;                  // 8256
    uncompress_sym_kernel<<<nblocks, THREADS>>>(comp, out, n, nb);
}